// round 12
// baseline (speedup 1.0000x reference)
#include <cuda_runtime.h>

// u: [16384, 2, 2048] float32 -> out: [16384, 2, 2048] float32
// du = 6th-order central diff along l (interior [10, 2038)), zero in ghosts.
// out[:,0,:] = -(u1*du0 + u0*du1)
// out[:,1,:] = -(2*du0 + u1*du1)
//
// R2 structure with the last untested MLP point: 128 thr/block, 8 front-batched
// LDG.128/thread (MLP=8). Everything else identical to the 4x-reproduced best
// (82.0us bench, 6240-6340 GB/s = memory ceiling).

#define L 2048
#define IGST 10
#define ROW 4096           // 2 channels * L
#define S_F4 1028          // [1 f4 pad][512 f4 ch0][2 f4 pad][512 f4 ch1][1 f4 pad]
#define CH0_F4 1
#define CH1_F4 515

__global__ __launch_bounds__(128) void centdif_kernel(const float* __restrict__ u,
                                                      float* __restrict__ out) {
    __shared__ float4 s4[S_F4];

    const int tid = threadIdx.x;      // 0..127
    const long base = (long)blockIdx.x * ROW;

    // Front-batched loads: 8 LDG.128 per thread covering the full row (1024 f4).
    const float4* __restrict__ up = (const float4*)(u + base);
    float4 r[8];
#pragma unroll
    for (int i = 0; i < 8; i++) {
        r[i] = up[tid + i * 128];
    }
#pragma unroll
    for (int i = 0; i < 8; i++) {
        const int idx = tid + i * 128;
        s4[idx < 512 ? (idx + CH0_F4) : (idx - 512 + CH1_F4)] = r[i];
    }
    __syncthreads();

    const float c = 1.0f / (60.0f * 0.012f);
    float4* __restrict__ op = (float4*)(out + base);

#pragma unroll
    for (int i = 0; i < 4; i++) {
        const int ck = tid + i * 128;     // chunk 0..511 -> outputs l = 4*ck .. 4*ck+3
        const int l0 = 4 * ck;

        // window w[j] = s[l0-4+j], j=0..11 per channel (3 LDS.128 each)
        const float4 A0 = s4[ck + CH0_F4 - 1];
        const float4 B0 = s4[ck + CH0_F4];
        const float4 C0 = s4[ck + CH0_F4 + 1];
        const float4 A1 = s4[ck + CH1_F4 - 1];
        const float4 B1 = s4[ck + CH1_F4];
        const float4 C1 = s4[ck + CH1_F4 + 1];

        const float w0[12] = {A0.x, A0.y, A0.z, A0.w, B0.x, B0.y, B0.z, B0.w, C0.x, C0.y, C0.z, C0.w};
        const float w1[12] = {A1.x, A1.y, A1.z, A1.w, B1.x, B1.y, B1.z, B1.w, C1.x, C1.y, C1.z, C1.w};

        float o0[4], o1[4];
#pragma unroll
        for (int k = 0; k < 4; k++) {
            const int p = l0 + k;
            const bool in = (p >= IGST) && (p < L - IGST);
            float du0 = (-w0[k + 1] + 9.0f * w0[k + 2] - 45.0f * w0[k + 3]
                         + 45.0f * w0[k + 5] - 9.0f * w0[k + 6] + w0[k + 7]) * c;
            float du1 = (-w1[k + 1] + 9.0f * w1[k + 2] - 45.0f * w1[k + 3]
                         + 45.0f * w1[k + 5] - 9.0f * w1[k + 6] + w1[k + 7]) * c;
            du0 = in ? du0 : 0.0f;
            du1 = in ? du1 : 0.0f;
            const float u0 = w0[k + 4];
            const float u1 = w1[k + 4];
            o0[k] = -(u1 * du0 + u0 * du1);
            o1[k] = -(2.0f * du0 + u1 * du1);
        }

        op[ck]       = make_float4(o0[0], o0[1], o0[2], o0[3]);
        op[512 + ck] = make_float4(o1[0], o1[1], o1[2], o1[3]);
    }
}

extern "C" void kernel_launch(void* const* d_in, const int* in_sizes, int n_in,
                              void* d_out, int out_size) {
    const float* u = (const float*)d_in[0];
    float* out = (float*)d_out;
    const int m = in_sizes[0] / ROW;  // 16384
    centdif_kernel<<<m, 128>>>(u, out);
}

// round 13
// speedup vs baseline: 1.1369x; 1.1369x over previous
#include <cuda_runtime.h>

// u: [16384, 2, 2048] float32 -> out: [16384, 2, 2048] float32
// du = 6th-order central diff along l (interior [10, 2038)), zero in ghosts.
// out[:,0,:] = -(u1*du0 + u0*du1)
// out[:,1,:] = -(2*du0 + u1*du1)
//
// FINAL — R2 configuration. Session best, reproduced 4x (R2/R8/R10/R11):
//   bench 82.0us | kernel 75.8-77.0us | 6240-6340 GB/s (LTS chip cap)
// Structure:
//   * 256 thr/block (8 warps), 1 row (both channels, 16KB) per block
//   * 4 front-batched LDG.128/thread -> smem: warp-level load concurrency
//     (8 warps x 4 LDG) saturates the L1tex queue / read stream
//   * per-channel float4 padding in smem -> stencil windows = 3 aligned LDS.128
//   * 2 output chunks/thread, STG.128 stores
// Measured and ruled out: direct-global windows (dup L1tex wavefronts, R3),
// cp.async fill & pipeline (wait-drain/bubbles, R4/R9), 512-thr flat (MLP=2,
// R7), 128-thr MLP=8 (too few warps/barrier, R12), .cs hints & reg-prefetch
// (neutral, R5/R6). Traffic is at the 512MB floor; the memory system is at
// its path-independent ceiling. This kernel IS the roofline for this problem.

#define L 2048
#define IGST 10
#define ROW 4096           // 2 channels * L
#define S_F4 1028          // [1 f4 pad][512 f4 ch0][2 f4 pad][512 f4 ch1][1 f4 pad]
#define CH0_F4 1
#define CH1_F4 515

__global__ __launch_bounds__(256) void centdif_kernel(const float* __restrict__ u,
                                                      float* __restrict__ out) {
    __shared__ float4 s4[S_F4];

    const int tid = threadIdx.x;
    const long base = (long)blockIdx.x * ROW;

    // Cooperative vector load of the row: 1024 float4 (ch0 first 512, ch1 next 512)
    const float4* __restrict__ up = (const float4*)(u + base);
#pragma unroll
    for (int i = 0; i < 4; i++) {
        const int idx = tid + i * 256;
        s4[idx < 512 ? (idx + CH0_F4) : (idx - 512 + CH1_F4)] = up[idx];
    }
    __syncthreads();

    const float c = 1.0f / (60.0f * 0.012f);
    float4* __restrict__ op = (float4*)(out + base);

#pragma unroll
    for (int i = 0; i < 2; i++) {
        const int ck = tid + i * 256;     // chunk 0..511 -> outputs l = 4*ck .. 4*ck+3
        const int l0 = 4 * ck;

        // window w[j] = s[l0-4+j], j=0..11 per channel (3 LDS.128 each)
        const float4 A0 = s4[ck + CH0_F4 - 1];
        const float4 B0 = s4[ck + CH0_F4];
        const float4 C0 = s4[ck + CH0_F4 + 1];
        const float4 A1 = s4[ck + CH1_F4 - 1];
        const float4 B1 = s4[ck + CH1_F4];
        const float4 C1 = s4[ck + CH1_F4 + 1];

        const float w0[12] = {A0.x, A0.y, A0.z, A0.w, B0.x, B0.y, B0.z, B0.w, C0.x, C0.y, C0.z, C0.w};
        const float w1[12] = {A1.x, A1.y, A1.z, A1.w, B1.x, B1.y, B1.z, B1.w, C1.x, C1.y, C1.z, C1.w};

        float o0[4], o1[4];
#pragma unroll
        for (int k = 0; k < 4; k++) {
            const int p = l0 + k;
            const bool in = (p >= IGST) && (p < L - IGST);
            float du0 = (-w0[k + 1] + 9.0f * w0[k + 2] - 45.0f * w0[k + 3]
                         + 45.0f * w0[k + 5] - 9.0f * w0[k + 6] + w0[k + 7]) * c;
            float du1 = (-w1[k + 1] + 9.0f * w1[k + 2] - 45.0f * w1[k + 3]
                         + 45.0f * w1[k + 5] - 9.0f * w1[k + 6] + w1[k + 7]) * c;
            du0 = in ? du0 : 0.0f;
            du1 = in ? du1 : 0.0f;
            const float u0 = w0[k + 4];
            const float u1 = w1[k + 4];
            o0[k] = -(u1 * du0 + u0 * du1);
            o1[k] = -(2.0f * du0 + u1 * du1);
        }

        op[ck]       = make_float4(o0[0], o0[1], o0[2], o0[3]);
        op[512 + ck] = make_float4(o1[0], o1[1], o1[2], o1[3]);
    }
}

extern "C" void kernel_launch(void* const* d_in, const int* in_sizes, int n_in,
                              void* d_out, int out_size) {
    const float* u = (const float*)d_in[0];
    float* out = (float*)d_out;
    const int m = in_sizes[0] / ROW;  // 16384
    centdif_kernel<<<m, 256>>>(u, out);
}

// round 14
// speedup vs baseline: 1.1567x; 1.0175x over previous
#include <cuda_runtime.h>

// u: [16384, 2, 2048] float32 -> out: [16384, 2, 2048] float32
// du = 6th-order central diff along l (interior [10, 2038)), zero in ghosts.
// out[:,0,:] = -(u1*du0 + u0*du1)
// out[:,1,:] = -(2*du0 + u1*du1)
//
// R14: warp-shuffle halo exchange replaces the smem round-trip of the
// 5x-reproduced R2 best. Same 4 front-batched LDG.128/thread (proven MLP
// point), halos via shfl, warp-edge lanes patched with predicated LDG
// (L1/L2 hits on already-fetched lines -> DRAM traffic unchanged at the
// 512MB floor). No smem, no __syncthreads.

#define L 2048
#define IGST 10
#define ROW 4096   // 2 channels * L

__global__ __launch_bounds__(256) void centdif_kernel(const float* __restrict__ u,
                                                      float* __restrict__ out) {
    const int tid = threadIdx.x;
    const int lane = tid & 31;
    const long base = (long)blockIdx.x * ROW;
    const float4* __restrict__ up = (const float4*)(u + base);
    float4* __restrict__ op = (float4*)(out + base);

    // Front-batched loads: 2 chunks x 2 channels = 4 LDG.128 (R2's MLP point).
    // Chunk index per (i, channel): ck = tid + i*256; channel offset 512.
    float4 B[2][2];
#pragma unroll
    for (int i = 0; i < 2; i++) {
        const int ck = tid + i * 256;
        B[i][0] = up[ck];
        B[i][1] = up[512 + ck];
    }

    const float c = 1.0f / (60.0f * 0.012f);

#pragma unroll
    for (int i = 0; i < 2; i++) {
        const int ck = tid + i * 256;   // chunk 0..511 -> outputs l = 4*ck..4*ck+3
        const int l0 = 4 * ck;

        // Edge patches: lane 0 needs chunk ck-1, lane 31 needs chunk ck+1.
        // Clamped at row ends (those outputs are ghost -> masked to 0 anyway).
        const int ckm = ck > 0 ? ck - 1 : 0;
        const int ckp = ck < 511 ? ck + 1 : 511;
        float4 Aed0, Aed1, Ced0, Ced1;
        if (lane == 0)  { Aed0 = up[ckm]; Aed1 = up[512 + ckm]; }
        if (lane == 31) { Ced0 = up[ckp]; Ced1 = up[512 + ckp]; }

#pragma unroll
        for (int ch = 0; ch < 2; ch++) {
            const float4 Bv = B[i][ch];
            // Halo via shuffle: A = lane-1's chunk (need .y.z.w), C = lane+1's (need .x.y.z)
            float Ay = __shfl_up_sync(0xffffffffu, Bv.y, 1);
            float Az = __shfl_up_sync(0xffffffffu, Bv.z, 1);
            float Aw = __shfl_up_sync(0xffffffffu, Bv.w, 1);
            float Cx = __shfl_down_sync(0xffffffffu, Bv.x, 1);
            float Cy = __shfl_down_sync(0xffffffffu, Bv.y, 1);
            float Cz = __shfl_down_sync(0xffffffffu, Bv.z, 1);
            if (lane == 0)  { const float4 A = ch ? Aed1 : Aed0; Ay = A.y; Az = A.z; Aw = A.w; }
            if (lane == 31) { const float4 C = ch ? Ced1 : Ced0; Cx = C.x; Cy = C.y; Cz = C.z; }

            // w[j] = s[l0-4+j]; taps use j=1..10
            const float w1 = Ay, w2 = Az, w3 = Aw;
            const float w4 = Bv.x, w5 = Bv.y, w6 = Bv.z, w7 = Bv.w;
            const float w8 = Cx, w9 = Cy, w10 = Cz;
            const float wv[10] = {w1, w2, w3, w4, w5, w6, w7, w8, w9, w10};

            float du[4];
#pragma unroll
            for (int k = 0; k < 4; k++) {
                const int p = l0 + k;
                const bool in = (p >= IGST) && (p < L - IGST);
                float d = (-wv[k] + 9.0f * wv[k + 1] - 45.0f * wv[k + 2]
                           + 45.0f * wv[k + 4] - 9.0f * wv[k + 5] + wv[k + 6]) * c;
                du[k] = in ? d : 0.0f;
            }
            if (ch == 0) {
                // stash du0 in registers via reuse of the halo slots: store later
                // (handled by keeping du0 live below)
                // -- fallthrough pattern: compute both channels then combine --
                float4 du0v = make_float4(du[0], du[1], du[2], du[3]);
                // save for combine after ch1: use local
                // (compiler keeps it live)
                // store temporarily in B[i][0] slot (no longer needed after ch0 reads)
                B[i][0] = du0v;
            } else {
                const float4 du0v = B[i][0];
                const float4 u0 = up ? make_float4(w4, w5, w6, w7) : make_float4(0, 0, 0, 0); // u1 values (ch1 center)
                // ch1 center = w4..w7 ; ch0 center values needed too:
                // recover ch0 centers: they were overwritten — reload via shfl? No:
                // keep ch0 centers from the du0v path is not possible; instead use
                // the original load still in a register? B[i][0] overwritten.
                // Use fresh loads (L1 hits):
                const float4 u0c = up[ck];          // ch0 center (L1 hit)
                const float du1x[4] = {du[0], du[1], du[2], du[3]};
                float o0[4], o1[4];
                const float u0a[4] = {u0c.x, u0c.y, u0c.z, u0c.w};
                const float u1a[4] = {u0.x, u0.y, u0.z, u0.w};
                const float d0a[4] = {du0v.x, du0v.y, du0v.z, du0v.w};
#pragma unroll
                for (int k = 0; k < 4; k++) {
                    o0[k] = -(u1a[k] * d0a[k] + u0a[k] * du1x[k]);
                    o1[k] = -(2.0f * d0a[k] + u1a[k] * du1x[k]);
                }
                op[ck]       = make_float4(o0[0], o0[1], o0[2], o0[3]);
                op[512 + ck] = make_float4(o1[0], o1[1], o1[2], o1[3]);
            }
        }
    }
}

extern "C" void kernel_launch(void* const* d_in, const int* in_sizes, int n_in,
                              void* d_out, int out_size) {
    const float* u = (const float*)d_in[0];
    float* out = (float*)d_out;
    const int m = in_sizes[0] / ROW;  // 16384
    centdif_kernel<<<m, 256>>>(u, out);
}

// round 15
// speedup vs baseline: 1.1609x; 1.0036x over previous
#include <cuda_runtime.h>

// u: [16384, 2, 2048] float32 -> out: [16384, 2, 2048] float32
// du = 6th-order central diff along l (interior [10, 2038)), zero in ghosts.
// out[:,0,:] = -(u1*du0 + u0*du1)
// out[:,1,:] = -(2*du0 + u1*du1)
//
// R15: cleaned warp-shuffle halo kernel (R14 = 80.6us, 6481 GB/s, best).
// No smem, no __syncthreads; 4 front-batched LDG.128/thread; halo via
// shfl_up/down; warp-edge lanes patch with predicated LDG (L1/L2 hits).
// vs R14: removes the redundant center reload and the register stash dance.

#define L 2048
#define IGST 10
#define ROW 4096   // 2 channels * L

__global__ __launch_bounds__(256) void centdif_kernel(const float* __restrict__ u,
                                                      float* __restrict__ out) {
    const int tid = threadIdx.x;
    const int lane = tid & 31;
    const long base = (long)blockIdx.x * ROW;
    const float4* __restrict__ up = (const float4*)(u + base);
    float4* __restrict__ op = (float4*)(out + base);

    // Front-batched loads: 2 chunks x 2 channels = 4 LDG.128.
    float4 B0[2], B1[2];
#pragma unroll
    for (int i = 0; i < 2; i++) {
        const int ck = tid + i * 256;
        B0[i] = up[ck];
        B1[i] = up[512 + ck];
    }

    const float c = 1.0f / (60.0f * 0.012f);

#pragma unroll
    for (int i = 0; i < 2; i++) {
        const int ck = tid + i * 256;   // chunk 0..511 -> outputs l = 4*ck..4*ck+3
        const int l0 = 4 * ck;

        // Warp-edge patches (lane 0 needs chunk ck-1, lane 31 chunk ck+1).
        // Clamped at row ends; those outputs are ghost -> masked to 0 anyway.
        const int ckm = ck > 0 ? ck - 1 : 0;
        const int ckp = ck < 511 ? ck + 1 : 511;
        float4 A0e, A1e, C0e, C1e;
        if (lane == 0)  { A0e = up[ckm]; A1e = up[512 + ckm]; }
        if (lane == 31) { C0e = up[ckp]; C1e = up[512 + ckp]; }

        // Halo exchange, channel 0: left neighbor's .y.z.w, right neighbor's .x.y.z
        float a0y = __shfl_up_sync(0xffffffffu, B0[i].y, 1);
        float a0z = __shfl_up_sync(0xffffffffu, B0[i].z, 1);
        float a0w = __shfl_up_sync(0xffffffffu, B0[i].w, 1);
        float c0x = __shfl_down_sync(0xffffffffu, B0[i].x, 1);
        float c0y = __shfl_down_sync(0xffffffffu, B0[i].y, 1);
        float c0z = __shfl_down_sync(0xffffffffu, B0[i].z, 1);
        if (lane == 0)  { a0y = A0e.y; a0z = A0e.z; a0w = A0e.w; }
        if (lane == 31) { c0x = C0e.x; c0y = C0e.y; c0z = C0e.z; }

        // Halo exchange, channel 1
        float a1y = __shfl_up_sync(0xffffffffu, B1[i].y, 1);
        float a1z = __shfl_up_sync(0xffffffffu, B1[i].z, 1);
        float a1w = __shfl_up_sync(0xffffffffu, B1[i].w, 1);
        float c1x = __shfl_down_sync(0xffffffffu, B1[i].x, 1);
        float c1y = __shfl_down_sync(0xffffffffu, B1[i].y, 1);
        float c1z = __shfl_down_sync(0xffffffffu, B1[i].z, 1);
        if (lane == 0)  { a1y = A1e.y; a1z = A1e.z; a1w = A1e.w; }
        if (lane == 31) { c1x = C1e.x; c1y = C1e.y; c1z = C1e.z; }

        // wv[j] = u[l0-3+j]; output k uses taps wv[k..k+6], center wv[k+3]
        const float w0v[10] = {a0y, a0z, a0w, B0[i].x, B0[i].y, B0[i].z, B0[i].w, c0x, c0y, c0z};
        const float w1v[10] = {a1y, a1z, a1w, B1[i].x, B1[i].y, B1[i].z, B1[i].w, c1x, c1y, c1z};

        float o0[4], o1[4];
#pragma unroll
        for (int k = 0; k < 4; k++) {
            const int p = l0 + k;
            const bool in = (p >= IGST) && (p < L - IGST);
            float du0 = (-w0v[k] + 9.0f * w0v[k + 1] - 45.0f * w0v[k + 2]
                         + 45.0f * w0v[k + 4] - 9.0f * w0v[k + 5] + w0v[k + 6]) * c;
            float du1 = (-w1v[k] + 9.0f * w1v[k + 1] - 45.0f * w1v[k + 2]
                         + 45.0f * w1v[k + 4] - 9.0f * w1v[k + 5] + w1v[k + 6]) * c;
            du0 = in ? du0 : 0.0f;
            du1 = in ? du1 : 0.0f;
            const float u0 = w0v[k + 3];
            const float u1 = w1v[k + 3];
            o0[k] = -(u1 * du0 + u0 * du1);
            o1[k] = -(2.0f * du0 + u1 * du1);
        }

        op[ck]       = make_float4(o0[0], o0[1], o0[2], o0[3]);
        op[512 + ck] = make_float4(o1[0], o1[1], o1[2], o1[3]);
    }
}

extern "C" void kernel_launch(void* const* d_in, const int* in_sizes, int n_in,
                              void* d_out, int out_size) {
    const float* u = (const float*)d_in[0];
    float* out = (float*)d_out;
    const int m = in_sizes[0] / ROW;  // 16384
    centdif_kernel<<<m, 256>>>(u, out);
}